// round 10
// baseline (speedup 1.0000x reference)
#include <cuda_runtime.h>
#include <cstdint>

#define BB 2
#define MM 4
#define CCH 64
#define VV 110592
#define KK 4
#define CB 8                 // channels per block
#define CG 8                 // channel groups
#define VS 6                 // V splits
#define VCHUNK (VV/VS)       // 18432 elems -> 73728 B per channel slice
#define SELEM 2048           // elems per stage (8192 B)
#define NSPC 9               // stages per channel
#define GTOT (CB*NSPC)       // 72 global stages
#define NSLOT 8              // ring slots
#define AHEAD 6              // issue-ahead depth
#define NBLK (BB*MM*CG*VS)   // 384
#define THREADS 512
#define NWARP 16
#define EPSL 1e-6f

#define STAGE_B 8192
#define DYN_BYTES (NSLOT*STAGE_B)   // 65536

// ---- scratch (no allocations allowed) ----
__device__ float g_numpart[NBLK * 32];
__device__ float g_twpart[BB*MM*VS*KK];
__device__ float g_cntpart[BB*VS*KK];
__device__ unsigned g_ctr;              // zero-init; reset each launch

extern __shared__ char dynsm[];

#define BULK(dst, src, nbytes, mbar) \
    asm volatile("cp.async.bulk.shared::cluster.global.mbarrier::complete_tx::bytes [%0], [%1], %2, [%3];" \
                 :: "r"(dst), "l"(src), "r"(nbytes), "r"(mbar) : "memory")
#define MB_INIT(mbar, cnt) \
    asm volatile("mbarrier.init.shared.b64 [%0], %1;" :: "r"(mbar), "r"(cnt) : "memory")
#define MB_EXPECT_TX(mbar, tx) \
    asm volatile("mbarrier.arrive.expect_tx.shared.b64 _, [%0], %1;" :: "r"(mbar), "r"(tx) : "memory")
#define MB_ARRIVE(mbar) \
    asm volatile("mbarrier.arrive.shared.b64 _, [%0];" :: "r"(mbar) : "memory")

__device__ __forceinline__ void mb_wait_acq(uint32_t mbar, uint32_t parity) {
    uint32_t done = 0;
    while (!done) {
        asm volatile(
            "{\n\t.reg .pred p;\n\t"
            "mbarrier.try_wait.parity.acquire.cta.shared::cta.b64 p, [%1], %2, 0x989680;\n\t"
            "selp.b32 %0, 1, 0, p;\n\t}"
            : "=r"(done) : "r"(mbar), "r"(parity) : "memory");
    }
}
__device__ __forceinline__ void mb_wait_rlx(uint32_t mbar, uint32_t parity) {
    uint32_t done = 0;
    while (!done) {
        asm volatile(
            "{\n\t.reg .pred p;\n\t"
            "mbarrier.try_wait.parity.relaxed.cta.shared::cta.b64 p, [%1], %2, 0x989680;\n\t"
            "selp.b32 %0, 1, 0, p;\n\t}"
            : "=r"(done) : "r"(mbar), "r"(parity) : "memory");
    }
}

__global__ __launch_bounds__(THREADS, 1) void kmain(const float* __restrict__ f,
                                                    const float* __restrict__ w,
                                                    const int*   __restrict__ tw_words,
                                                    float* __restrict__ out) {
    const int bm = blockIdx.x;   // 0..7 (b*4+m)
    const int cg = blockIdx.y;   // 0..7
    const int vs = blockIdx.z;   // 0..5
    const int b  = bm >> 2;
    const int tid = threadIdx.x;
    const int lane = tid & 31, wid = tid >> 5;

    __shared__ float sred[NWARP][32];
    __shared__ float s_proto[2048];
    __shared__ float s_tw[32];
    __shared__ float s_cnt[8];
    __shared__ float s_aterm[48], s_acnt[48], s_sterm[48], s_scnt[48];
    __shared__ int   s_last;
    __shared__ __align__(8) unsigned long long mbars[2*NSLOT];  // full[0..7], empty[8..15]

    // ---- dtype detect: one high-word per thread ----
    const int is64 = (__syncthreads_or(tw_words[2*tid + 1]) == 0);

    const uint32_t mb0 = (uint32_t)__cvta_generic_to_shared(mbars);
#define FULLB(i)  (mb0 + (i)*8)
#define EMPTYB(i) (mb0 + 64 + (i)*8)

    if (tid == 0) {
#pragma unroll
        for (int i = 0; i < NSLOT; i++) { MB_INIT(FULLB(i), 1); MB_INIT(EMPTYB(i), NWARP); }
    }
    __syncthreads();

    const long vbase = (long)vs * VCHUNK;
    const char*  fsrcB = (const char*)(f + ((long)bm*CCH + (long)cg*CB)*VV + vbase);
    const float* wsrc  = w + (long)bm*VV + vbase + tid*4;   // float4/thread/stage
    const int4*  t32   = (const int4*)((const char*)tw_words + ((long)b*VV + vbase)*4) + tid;
    const int4*  t64   = (const int4*)((const char*)tw_words + ((long)b*VV + vbase)*8) + tid*2;

    const uint32_t sm0 = (uint32_t)__cvta_generic_to_shared(dynsm);

    // producer running state (meaningful in tid 0 only): sequential within a
    // channel, jump to next channel every NSPC stages
    long ioff = 0;   // byte offset into fsrcB for next issued stage
    int  isc  = 0;   // stage-within-channel of next issued stage

#define ISSUE(slot) do {                                                  \
        MB_EXPECT_TX(FULLB(slot), STAGE_B);                               \
        BULK(sm0 + (slot)*STAGE_B, fsrcB + ioff, STAGE_B, FULLB(slot));   \
        ioff += STAGE_B;                                                  \
        if (++isc == NSPC) { isc = 0; ioff += (long)VV*4 - NSPC*STAGE_B; }\
    } while (0)

    float acc[CB][KK];
#pragma unroll
    for (int cc = 0; cc < CB; cc++)
#pragma unroll
        for (int k = 0; k < KK; k++) acc[cc][k] = 0.f;
    float twl[KK] = {0.f,0.f,0.f,0.f};
    float cl [KK] = {0.f,0.f,0.f,0.f};
    const bool doTW  = (cg == 0);
    const bool doCNT = doTW && ((bm & 3) == 0);

    if (tid == 0) {
#pragma unroll
        for (int j = 0; j < AHEAD; j++) ISSUE(j);   // stages 0..5 (all in channel 0)
    }

    // w/t register prefetch for stage s=0
    float4 wb = *(const float4*)(wsrc);
    int4 ta = {0,0,0,0}, tb2 = {0,0,0,0};
    if (is64) { ta = t64[0]; tb2 = t64[1]; }
    else      { ta = t32[0]; }

#pragma unroll
    for (int cc = 0; cc < CB; cc++) {
        float acc4[KK] = {0.f,0.f,0.f,0.f};
#pragma unroll 1
        for (int s = 0; s < NSPC; s++) {
            const int g = cc*NSPC + s;
            // ---- producer: issue stage j = g+AHEAD into slot j%8 ----
            const int j = g + AHEAD;
            if (tid == 0 && j < GTOT) {
                const int jslot = j & (NSLOT-1);
                if (j >= NSLOT) mb_wait_rlx(EMPTYB(jslot), ((j >> 3) - 1) & 1);
                ISSUE(jslot);
            }
            // ---- prefetch next stage's w/t (s' = (s+1)%9; reread across channels hits L1/L2) ----
            const int sn = (s + 1 == NSPC) ? 0 : s + 1;
            float4 wn = *(const float4*)(wsrc + sn*SELEM);
            int4 tna = {0,0,0,0}, tnb = {0,0,0,0};
            if (is64) { tna = t64[sn*1024]; tnb = t64[sn*1024 + 1]; }
            else      { tna = t32[sn*512]; }

            // ---- consumer: wait stage g (slot g%8, phase (g/8)&1) ----
            const int cslot = g & (NSLOT-1);
            mb_wait_acq(FULLB(cslot), (g >> 3) & 1);
            const char* sb = dynsm + cslot*STAGE_B;

            int t0, t1, t2, t3;
            if (is64) { t0 = ta.x; t1 = ta.z; t2 = tb2.x; t3 = tb2.z; }
            else      { t0 = ta.x; t1 = ta.y; t2 = ta.z;  t3 = ta.w; }
            const int   ts[4] = { t0, t1, t2, t3 };
            const float ws[4] = { wb.x, wb.y, wb.z, wb.w };
            float msk[4][KK];
#pragma unroll
            for (int jj = 0; jj < 4; jj++)
#pragma unroll
                for (int k = 0; k < KK; k++)
                    msk[jj][k] = (ts[jj] == k) ? ws[jj] : 0.f;

            if (cc == 0 && doTW) {
#pragma unroll
                for (int k = 0; k < KK; k++)
                    twl[k] += (msk[0][k] + msk[1][k]) + (msk[2][k] + msk[3][k]);
            }
            if (cc == 0 && doCNT) {
#pragma unroll
                for (int k = 0; k < KK; k++) {
                    float c0 = (t0==k)?1.f:0.f, c1 = (t1==k)?1.f:0.f;
                    float c2 = (t2==k)?1.f:0.f, c3 = (t3==k)?1.f:0.f;
                    cl[k] += (c0+c1)+(c2+c3);
                }
            }

            float4 fv = *(const float4*)(sb + tid*16);
            const float fs[4] = { fv.x, fv.y, fv.z, fv.w };
#pragma unroll
            for (int k = 0; k < KK; k++) {
                acc4[k] += fs[0]*msk[0][k];
                acc4[k] += fs[1]*msk[1][k];
                acc4[k] += fs[2]*msk[2][k];
                acc4[k] += fs[3]*msk[3][k];
            }
            if (lane == 0) MB_ARRIVE(EMPTYB(cslot));

            wb = wn; ta = tna; tb2 = tnb;
        }
#pragma unroll
        for (int k = 0; k < KK; k++) acc[cc][k] = acc4[k];
    }

    // ---- block-reduce 32 accumulators over 16 warps ----
#pragma unroll
    for (int cc = 0; cc < CB; cc++)
#pragma unroll
        for (int k = 0; k < KK; k++)
#pragma unroll
            for (int off = 16; off > 0; off >>= 1)
                acc[cc][k] += __shfl_down_sync(0xffffffffu, acc[cc][k], off);
    if (lane == 0) {
#pragma unroll
        for (int cc = 0; cc < CB; cc++)
#pragma unroll
            for (int k = 0; k < KK; k++) sred[wid][cc*KK + k] = acc[cc][k];
    }
    __syncthreads();
    const int bid = (bm*CG + cg)*VS + vs;
    if (tid < 32) {
        float s = 0.f;
#pragma unroll
        for (int ww = 0; ww < NWARP; ww++) s += sred[ww][tid];
        g_numpart[bid*32 + tid] = s;
    }
    __syncthreads();

    // ---- block-reduce tw/cnt ----
    {
        float vals[8];
#pragma unroll
        for (int jv = 0; jv < 4; jv++) { vals[jv] = twl[jv]; vals[4+jv] = cl[jv]; }
#pragma unroll
        for (int jv = 0; jv < 8; jv++)
#pragma unroll
            for (int off = 16; off > 0; off >>= 1)
                vals[jv] += __shfl_down_sync(0xffffffffu, vals[jv], off);
        if (lane == 0) {
#pragma unroll
            for (int jv = 0; jv < 8; jv++) sred[wid][jv] = vals[jv];
        }
        __syncthreads();
        if (tid < 8) {
            float s = 0.f;
#pragma unroll
            for (int ww = 0; ww < NWARP; ww++) s += sred[ww][tid];
            if (tid < 4) {
                if (doTW) g_twpart[(bm*VS + vs)*4 + tid] = s;
            } else {
                if (doCNT) g_cntpart[(b*VS + vs)*4 + (tid-4)] = s;
            }
        }
    }

    // ---- last-block-done finalize ----
    __threadfence();
    __syncthreads();
    if (tid == 0) {
        unsigned old = atomicAdd(&g_ctr, 1u);
        s_last = (old == (unsigned)(NBLK - 1));
    }
    __syncthreads();
    if (!s_last) return;

    // Phase A: tw (32) + cnt (8)
    if (tid < 32) {
        int bm_ = tid >> 2, k = tid & 3;
        float s = 0.f;
        for (int v = 0; v < VS; v++) s += g_twpart[(bm_*VS + v)*4 + k];
        s_tw[tid] = s + EPSL;
    } else if (tid < 40) {
        int jv = tid - 32, b_ = jv >> 2, k = jv & 3;
        float s = 0.f;
        for (int v = 0; v < VS; v++) s += g_cntpart[(b_*VS + v)*4 + k];
        s_cnt[jv] = s;
    }
    __syncthreads();

    // Phase B: proto raw = num / tw
    for (int cell = tid; cell < 2048; cell += THREADS) {
        int bm_ = cell >> 8;
        int rem = cell & 255;
        int c = rem >> 2, k = rem & 3;
        int cg_ = c >> 3, cc = c & 7;
        float s = 0.f;
        for (int v = 0; v < VS; v++)
            s += g_numpart[((bm_*CG + cg_)*VS + v)*32 + cc*4 + k];
        s_proto[(bm_*4 + k)*64 + c] = s / s_tw[bm_*4 + k];
    }
    __syncthreads();

    // Phase C: normalize 32 rows (16 warps x 2 rows)
#pragma unroll
    for (int jv = 0; jv < 2; jv++) {
        int r = wid + NWARP*jv;
        float v1 = s_proto[r*64 + lane];
        float v2 = s_proto[r*64 + lane + 32];
        float ss = v1*v1 + v2*v2;
#pragma unroll
        for (int off = 16; off > 0; off >>= 1)
            ss += __shfl_xor_sync(0xffffffffu, ss, off);
        float norm = fmaxf(sqrtf(fmaxf(ss, 1e-24f)), 1e-12f);
        float inv = 1.f / norm;
        s_proto[r*64 + lane]      = v1 * inv;
        s_proto[r*64 + lane + 32] = v2 * inv;
    }
    __syncthreads();

    // Phase D: 96 pair dot products (16 warps x 6 pairs)
    {
        const int p1t[6] = {0,0,0,1,1,2};
        const int p2t[6] = {1,2,3,2,3,3};
        for (int p = wid; p < 96; p += NWARP) {
            int r1, r2, outidx;
            bool val;
            bool isAlign = (p < 48);
            float om = 1.f;
            if (isAlign) {
                int pa = p;
                int b_ = pa / 24; int rem = pa % 24;
                int mp = rem >> 2, k = rem & 3;
                int m = p1t[mp], n = p2t[mp];
                r1 = (b_*4 + m)*4 + k;
                r2 = (b_*4 + n)*4 + k;
                val = (s_cnt[b_*4 + k] >= 1.f) && (k != 0);
                float cd = s_cnt[b_*4 + k] + EPSL;
                om = (s_tw[r1] / cd) * (s_tw[r2] / cd);
                outidx = pa;
            } else {
                int ps = p - 48;
                int b_ = ps / 24; int rem = ps % 24;
                int m = rem / 6, kp = rem % 6;
                int k1 = p1t[kp], k2 = p2t[kp];
                r1 = (b_*4 + m)*4 + k1;
                r2 = (b_*4 + m)*4 + k2;
                val = (s_cnt[b_*4 + k1] >= 1.f) && (k1 != 0) &&
                      (s_cnt[b_*4 + k2] >= 1.f) && (k2 != 0);
                outidx = ps;
            }
            float a1 = s_proto[r1*64 + lane],      b1 = s_proto[r2*64 + lane];
            float a2 = s_proto[r1*64 + lane + 32], b2 = s_proto[r2*64 + lane + 32];
            float dot = a1*b1 + a2*b2;
#pragma unroll
            for (int off = 16; off > 0; off >>= 1)
                dot += __shfl_xor_sync(0xffffffffu, dot, off);
            if (lane == 0) {
                if (isAlign) {
                    s_aterm[outidx] = val ? om * fmaxf(0.9f - dot, 0.f) : 0.f;
                    s_acnt[outidx]  = val ? 1.f : 0.f;
                } else {
                    s_sterm[outidx] = val ? fmaxf(dot - 0.1f, 0.f) : 0.f;
                    s_scnt[outidx]  = val ? 1.f : 0.f;
                }
            }
        }
    }
    __syncthreads();

    // Phase E: scalar loss + counter reset
    if (tid == 0) {
        float as = 0.f, ac = 0.f, ssum = 0.f, sc = 0.f;
        for (int i = 0; i < 48; i++) { as += s_aterm[i]; ac += s_acnt[i]; }
        for (int i = 0; i < 48; i++) { ssum += s_sterm[i]; sc += s_scnt[i]; }
        out[0] = as / (ac + EPSL) + ssum / (sc + EPSL);
        g_ctr = 0;
    }
}

extern "C" void kernel_launch(void* const* d_in, const int* in_sizes, int n_in,
                              void* d_out, int out_size) {
    const float* feats   = (const float*)d_in[0];
    const float* weights = (const float*)d_in[1];
    const int*   tgt_w   = (const int*)d_in[2];   // int32 or int64; detected on-device
    float* out = (float*)d_out;

    cudaFuncSetAttribute(kmain, cudaFuncAttributeMaxDynamicSharedMemorySize, DYN_BYTES);
    kmain<<<dim3(BB*MM, CG, VS), THREADS, DYN_BYTES>>>(feats, weights, tgt_w, out);
}

// round 11
// speedup vs baseline: 1.8713x; 1.8713x over previous
#include <cuda_runtime.h>
#include <cstdint>

#define BB 2
#define MM 4
#define CCH 64
#define VV 110592
#define KK 4
#define CB 8                 // channels per block (4 TMA + 4 LDG)
#define CBT 4                // TMA channels
#define CG 8                 // channel groups
#define VS 6                 // V splits
#define VCHUNK (VV/VS)       // 18432 elems per channel slice
#define SELEM 1536           // elems per stage
#define NSPC 12              // stages
#define NSLOT 6              // ring slots
#define AHEAD 5              // issue-ahead depth
#define NBLK (BB*MM*CG*VS)   // 384
#define THREADS 384
#define NWARP 12
#define EPSL 1e-6f

#define CH_B 6144            // bytes per channel per stage
#define STAGE_B (CBT*CH_B)   // 24576
#define DYN_BYTES (NSLOT*STAGE_B)   // 147456

// ---- scratch (no allocations allowed) ----
__device__ float g_numpart[NBLK * 32];
__device__ float g_twpart[BB*MM*VS*KK];
__device__ float g_cntpart[BB*VS*KK];
__device__ unsigned g_ctr;              // zero-init; reset each launch

extern __shared__ char dynsm[];

#define BULK(dst, src, nbytes, mbar) \
    asm volatile("cp.async.bulk.shared::cluster.global.mbarrier::complete_tx::bytes [%0], [%1], %2, [%3];" \
                 :: "r"(dst), "l"(src), "r"(nbytes), "r"(mbar) : "memory")
#define MB_INIT(mbar, cnt) \
    asm volatile("mbarrier.init.shared.b64 [%0], %1;" :: "r"(mbar), "r"(cnt) : "memory")
#define MB_EXPECT_TX(mbar, tx) \
    asm volatile("mbarrier.arrive.expect_tx.shared.b64 _, [%0], %1;" :: "r"(mbar), "r"(tx) : "memory")
#define MB_ARRIVE(mbar) \
    asm volatile("mbarrier.arrive.shared.b64 _, [%0];" :: "r"(mbar) : "memory")

__device__ __forceinline__ void mb_wait_acq(uint32_t mbar, uint32_t parity) {
    uint32_t done = 0;
    while (!done) {
        asm volatile(
            "{\n\t.reg .pred p;\n\t"
            "mbarrier.try_wait.parity.acquire.cta.shared::cta.b64 p, [%1], %2, 0x989680;\n\t"
            "selp.b32 %0, 1, 0, p;\n\t}"
            : "=r"(done) : "r"(mbar), "r"(parity) : "memory");
    }
}
__device__ __forceinline__ void mb_wait_rlx(uint32_t mbar, uint32_t parity) {
    uint32_t done = 0;
    while (!done) {
        asm volatile(
            "{\n\t.reg .pred p;\n\t"
            "mbarrier.try_wait.parity.relaxed.cta.shared::cta.b64 p, [%1], %2, 0x989680;\n\t"
            "selp.b32 %0, 1, 0, p;\n\t}"
            : "=r"(done) : "r"(mbar), "r"(parity) : "memory");
    }
}

__global__ __launch_bounds__(THREADS, 1) void kmain(const float* __restrict__ f,
                                                    const float* __restrict__ w,
                                                    const int*   __restrict__ tw_words,
                                                    float* __restrict__ out) {
    const int bm = blockIdx.x;   // 0..7 (b*4+m)
    const int cg = blockIdx.y;   // 0..7
    const int vs = blockIdx.z;   // 0..5
    const int b  = bm >> 2;
    const int tid = threadIdx.x;
    const int lane = tid & 31, wid = tid >> 5;

    __shared__ float sred[NWARP][32];
    __shared__ float s_proto[2048];
    __shared__ float s_tw[32];
    __shared__ float s_cnt[8];
    __shared__ float s_aterm[48], s_acnt[48], s_sterm[48], s_scnt[48];
    __shared__ int   s_last;
    __shared__ __align__(8) unsigned long long mbars[2*NSLOT];

    // ---- dtype detect: one high-word per thread ----
    const int is64 = (__syncthreads_or(tw_words[2*tid + 1]) == 0);

    const uint32_t mb0 = (uint32_t)__cvta_generic_to_shared(mbars);
#define FULLB(i)  (mb0 + (i)*8)
#define EMPTYB(i) (mb0 + 48 + (i)*8)

    if (tid == 0) {
#pragma unroll
        for (int i = 0; i < NSLOT; i++) { MB_INIT(FULLB(i), 1); MB_INIT(EMPTYB(i), NWARP); }
    }
    __syncthreads();

    const long vbase = (long)vs * VCHUNK;
    const char*  fsrcB = (const char*)(f + ((long)bm*CCH + (long)cg*CB)*VV + vbase);
    const float* wsrc  = w + (long)bm*VV + vbase;
    const int4*  t32   = (const int4*)((const char*)tw_words + ((long)b*VV + vbase)*4) + tid;
    const int4*  t64   = (const int4*)((const char*)tw_words + ((long)b*VV + vbase)*8) + tid*2;

    const uint32_t sm0 = (uint32_t)__cvta_generic_to_shared(dynsm);

    // TMA: channels 0..3.  LDG: channels 4..7.
#define ISSUE(j, slot) do {                                                     \
        const uint32_t sb_ = sm0 + (slot)*STAGE_B;                              \
        MB_EXPECT_TX(FULLB(slot), STAGE_B);                                     \
        _Pragma("unroll")                                                       \
        for (int cc_ = 0; cc_ < CBT; cc_++)                                     \
            BULK(sb_ + cc_*CH_B, fsrcB + (long)(j)*CH_B + (long)cc_*(VV*4), CH_B, FULLB(slot)); \
    } while (0)

    float acc[CB][KK];
#pragma unroll
    for (int cc = 0; cc < CB; cc++)
#pragma unroll
        for (int k = 0; k < KK; k++) acc[cc][k] = 0.f;
    float twl[KK] = {0.f,0.f,0.f,0.f};
    float cl [KK] = {0.f,0.f,0.f,0.f};
    const bool doTW  = (cg == 0);
    const bool doCNT = doTW && ((bm & 3) == 0);

    if (tid == 0) {
#pragma unroll
        for (int j = 0; j < AHEAD; j++) ISSUE(j, j);
    }

    // w/t register prefetch for stage 0
    float4 wb = *(const float4*)(wsrc + tid*4);
    int4 ta = {0,0,0,0}, tb2 = {0,0,0,0};
    if (is64) { ta = t64[0]; tb2 = t64[1]; }
    else      { ta = t32[0]; }

#pragma unroll 1
    for (int s = 0; s < NSPC; s++) {
        // ---- LDG path: issue loads for channels 4..7, stage s (consumed below) ----
        float4 lv[4];
#pragma unroll
        for (int jc = 0; jc < 4; jc++)
            lv[jc] = *(const float4*)(fsrcB + (long)(4+jc)*(VV*4) + (long)s*CH_B + tid*16);

        // ---- producer: issue TMA stage j = s+AHEAD into slot j%6 ----
        const int j = s + AHEAD;
        if (tid == 0 && j < NSPC) {
            const int jslot = j % NSLOT;
            if (j >= NSLOT) mb_wait_rlx(EMPTYB(jslot), ((j / NSLOT) - 1) & 1);
            ISSUE(j, jslot);
        }
        // ---- prefetch next stage's w/t into regs ----
        float4 wn = {0.f,0.f,0.f,0.f};
        int4 tna = {0,0,0,0}, tnb = {0,0,0,0};
        if (s + 1 < NSPC) {
            wn = *(const float4*)(wsrc + (s+1)*SELEM + tid*4);
            if (is64) { tna = t64[(s+1)*768]; tnb = t64[(s+1)*768 + 1]; }
            else      { tna = t32[(s+1)*384]; }
        }

        // ---- consumer: wait TMA stage s ----
        const int cslot = s % NSLOT;
        mb_wait_acq(FULLB(cslot), (s / NSLOT) & 1);
        const char* sb = dynsm + cslot*STAGE_B;

        int t0, t1, t2, t3;
        if (is64) { t0 = ta.x; t1 = ta.z; t2 = tb2.x; t3 = tb2.z; }
        else      { t0 = ta.x; t1 = ta.y; t2 = ta.z;  t3 = ta.w; }
        const int   ts[4] = { t0, t1, t2, t3 };
        const float ws[4] = { wb.x, wb.y, wb.z, wb.w };
        float msk[4][KK];
#pragma unroll
        for (int jj = 0; jj < 4; jj++)
#pragma unroll
            for (int k = 0; k < KK; k++)
                msk[jj][k] = (ts[jj] == k) ? ws[jj] : 0.f;

        if (doTW) {
#pragma unroll
            for (int k = 0; k < KK; k++)
                twl[k] += (msk[0][k] + msk[1][k]) + (msk[2][k] + msk[3][k]);
        }
        if (doCNT) {
#pragma unroll
            for (int k = 0; k < KK; k++) {
                float c0 = (t0==k)?1.f:0.f, c1 = (t1==k)?1.f:0.f;
                float c2 = (t2==k)?1.f:0.f, c3 = (t3==k)?1.f:0.f;
                cl[k] += (c0+c1)+(c2+c3);
            }
        }

        // TMA channels 0..3 (from smem)
#pragma unroll
        for (int cc = 0; cc < CBT; cc++) {
            float4 fv = *(const float4*)(sb + cc*CH_B + tid*16);
            const float fs[4] = { fv.x, fv.y, fv.z, fv.w };
#pragma unroll
            for (int k = 0; k < KK; k++) {
                acc[cc][k] += fs[0]*msk[0][k];
                acc[cc][k] += fs[1]*msk[1][k];
                acc[cc][k] += fs[2]*msk[2][k];
                acc[cc][k] += fs[3]*msk[3][k];
            }
        }
        if (lane == 0) MB_ARRIVE(EMPTYB(cslot));

        // LDG channels 4..7 (from registers; loads had the whole wait to land)
#pragma unroll
        for (int jc = 0; jc < 4; jc++) {
            const float fs[4] = { lv[jc].x, lv[jc].y, lv[jc].z, lv[jc].w };
#pragma unroll
            for (int k = 0; k < KK; k++) {
                acc[4+jc][k] += fs[0]*msk[0][k];
                acc[4+jc][k] += fs[1]*msk[1][k];
                acc[4+jc][k] += fs[2]*msk[2][k];
                acc[4+jc][k] += fs[3]*msk[3][k];
            }
        }

        wb = wn; ta = tna; tb2 = tnb;
    }

    // ---- block-reduce 32 accumulators over 12 warps ----
#pragma unroll
    for (int cc = 0; cc < CB; cc++)
#pragma unroll
        for (int k = 0; k < KK; k++)
#pragma unroll
            for (int off = 16; off > 0; off >>= 1)
                acc[cc][k] += __shfl_down_sync(0xffffffffu, acc[cc][k], off);
    if (lane == 0) {
#pragma unroll
        for (int cc = 0; cc < CB; cc++)
#pragma unroll
            for (int k = 0; k < KK; k++) sred[wid][cc*KK + k] = acc[cc][k];
    }
    __syncthreads();
    const int bid = (bm*CG + cg)*VS + vs;
    if (tid < 32) {
        float s = 0.f;
#pragma unroll
        for (int ww = 0; ww < NWARP; ww++) s += sred[ww][tid];
        g_numpart[bid*32 + tid] = s;
    }
    __syncthreads();

    // ---- block-reduce tw/cnt ----
    {
        float vals[8];
#pragma unroll
        for (int jv = 0; jv < 4; jv++) { vals[jv] = twl[jv]; vals[4+jv] = cl[jv]; }
#pragma unroll
        for (int jv = 0; jv < 8; jv++)
#pragma unroll
            for (int off = 16; off > 0; off >>= 1)
                vals[jv] += __shfl_down_sync(0xffffffffu, vals[jv], off);
        if (lane == 0) {
#pragma unroll
            for (int jv = 0; jv < 8; jv++) sred[wid][jv] = vals[jv];
        }
        __syncthreads();
        if (tid < 8) {
            float s = 0.f;
#pragma unroll
            for (int ww = 0; ww < NWARP; ww++) s += sred[ww][tid];
            if (tid < 4) {
                if (doTW) g_twpart[(bm*VS + vs)*4 + tid] = s;
            } else {
                if (doCNT) g_cntpart[(b*VS + vs)*4 + (tid-4)] = s;
            }
        }
    }

    // ---- last-block-done finalize ----
    __threadfence();
    __syncthreads();
    if (tid == 0) {
        unsigned old = atomicAdd(&g_ctr, 1u);
        s_last = (old == (unsigned)(NBLK - 1));
    }
    __syncthreads();
    if (!s_last) return;

    // Phase A: tw (32) + cnt (8)
    if (tid < 32) {
        int bm_ = tid >> 2, k = tid & 3;
        float s = 0.f;
        for (int v = 0; v < VS; v++) s += g_twpart[(bm_*VS + v)*4 + k];
        s_tw[tid] = s + EPSL;
    } else if (tid < 40) {
        int jv = tid - 32, b_ = jv >> 2, k = jv & 3;
        float s = 0.f;
        for (int v = 0; v < VS; v++) s += g_cntpart[(b_*VS + v)*4 + k];
        s_cnt[jv] = s;
    }
    __syncthreads();

    // Phase B: proto raw = num / tw
    for (int cell = tid; cell < 2048; cell += THREADS) {
        int bm_ = cell >> 8;
        int rem = cell & 255;
        int c = rem >> 2, k = rem & 3;
        int cg_ = c >> 3, cc = c & 7;
        float s = 0.f;
        for (int v = 0; v < VS; v++)
            s += g_numpart[((bm_*CG + cg_)*VS + v)*32 + cc*4 + k];
        s_proto[(bm_*4 + k)*64 + c] = s / s_tw[bm_*4 + k];
    }
    __syncthreads();

    // Phase C: normalize 32 rows
    for (int r = wid; r < 32; r += NWARP) {
        float v1 = s_proto[r*64 + lane];
        float v2 = s_proto[r*64 + lane + 32];
        float ss = v1*v1 + v2*v2;
#pragma unroll
        for (int off = 16; off > 0; off >>= 1)
            ss += __shfl_xor_sync(0xffffffffu, ss, off);
        float norm = fmaxf(sqrtf(fmaxf(ss, 1e-24f)), 1e-12f);
        float inv = 1.f / norm;
        s_proto[r*64 + lane]      = v1 * inv;
        s_proto[r*64 + lane + 32] = v2 * inv;
    }
    __syncthreads();

    // Phase D: 96 pair dot products
    {
        const int p1t[6] = {0,0,0,1,1,2};
        const int p2t[6] = {1,2,3,2,3,3};
        for (int p = wid; p < 96; p += NWARP) {
            int r1, r2, outidx;
            bool val;
            bool isAlign = (p < 48);
            float om = 1.f;
            if (isAlign) {
                int pa = p;
                int b_ = pa / 24; int rem = pa % 24;
                int mp = rem >> 2, k = rem & 3;
                int m = p1t[mp], n = p2t[mp];
                r1 = (b_*4 + m)*4 + k;
                r2 = (b_*4 + n)*4 + k;
                val = (s_cnt[b_*4 + k] >= 1.f) && (k != 0);
                float cd = s_cnt[b_*4 + k] + EPSL;
                om = (s_tw[r1] / cd) * (s_tw[r2] / cd);
                outidx = pa;
            } else {
                int ps = p - 48;
                int b_ = ps / 24; int rem = ps % 24;
                int m = rem / 6, kp = rem % 6;
                int k1 = p1t[kp], k2 = p2t[kp];
                r1 = (b_*4 + m)*4 + k1;
                r2 = (b_*4 + m)*4 + k2;
                val = (s_cnt[b_*4 + k1] >= 1.f) && (k1 != 0) &&
                      (s_cnt[b_*4 + k2] >= 1.f) && (k2 != 0);
                outidx = ps;
            }
            float a1 = s_proto[r1*64 + lane],      b1 = s_proto[r2*64 + lane];
            float a2 = s_proto[r1*64 + lane + 32], b2 = s_proto[r2*64 + lane + 32];
            float dot = a1*b1 + a2*b2;
#pragma unroll
            for (int off = 16; off > 0; off >>= 1)
                dot += __shfl_xor_sync(0xffffffffu, dot, off);
            if (lane == 0) {
                if (isAlign) {
                    s_aterm[outidx] = val ? om * fmaxf(0.9f - dot, 0.f) : 0.f;
                    s_acnt[outidx]  = val ? 1.f : 0.f;
                } else {
                    s_sterm[outidx] = val ? fmaxf(dot - 0.1f, 0.f) : 0.f;
                    s_scnt[outidx]  = val ? 1.f : 0.f;
                }
            }
        }
    }
    __syncthreads();

    // Phase E: scalar loss + counter reset
    if (tid == 0) {
        float as = 0.f, ac = 0.f, ssum = 0.f, sc = 0.f;
        for (int i = 0; i < 48; i++) { as += s_aterm[i]; ac += s_acnt[i]; }
        for (int i = 0; i < 48; i++) { ssum += s_sterm[i]; sc += s_scnt[i]; }
        out[0] = as / (ac + EPSL) + ssum / (sc + EPSL);
        g_ctr = 0;
    }
}

extern "C" void kernel_launch(void* const* d_in, const int* in_sizes, int n_in,
                              void* d_out, int out_size) {
    const float* feats   = (const float*)d_in[0];
    const float* weights = (const float*)d_in[1];
    const int*   tgt_w   = (const int*)d_in[2];   // int32 or int64; detected on-device
    float* out = (float*)d_out;

    cudaFuncSetAttribute(kmain, cudaFuncAttributeMaxDynamicSharedMemorySize, DYN_BYTES);
    kmain<<<dim3(BB*MM, CG, VS), THREADS, DYN_BYTES>>>(feats, weights, tgt_w, out);
}

// round 12
// speedup vs baseline: 2.1690x; 1.1591x over previous
#include <cuda_runtime.h>
#include <cstdint>

#define BB 2
#define MM 4
#define CCH 64
#define VV 110592
#define KK 4
#define CB 8                 // channels per block (4 TMA + 4 LDG)
#define CBT 4                // TMA channels
#define CG 8                 // channel groups
#define VH 2                 // V halves
#define HALFV (VV/VH)        // 55296 elems per channel slice
#define SELEM 1536           // elems per stage
#define NSPC 36              // stages per block
#define NSLOT 6              // ring slots
#define AHEAD 5              // issue-ahead depth
#define NBLK (BB*MM*CG*VH)   // 128
#define THREADS 384
#define NWARP 12
#define EPSL 1e-6f

#define CH_B 6144            // bytes per TMA channel per stage
#define STAGE_B (CBT*CH_B)   // 24576
#define DYN_BYTES (NSLOT*STAGE_B)   // 147456

// ---- scratch (no allocations allowed) ----
__device__ float g_numpart[NBLK * 32];
__device__ float g_twpart[BB*MM*VH*KK];
__device__ float g_cntpart[BB*VH*KK];
__device__ unsigned g_ctr;              // zero-init; reset each launch

extern __shared__ char dynsm[];

#define BULK(dst, src, nbytes, mbar) \
    asm volatile("cp.async.bulk.shared::cluster.global.mbarrier::complete_tx::bytes [%0], [%1], %2, [%3];" \
                 :: "r"(dst), "l"(src), "r"(nbytes), "r"(mbar) : "memory")
#define MB_INIT(mbar, cnt) \
    asm volatile("mbarrier.init.shared.b64 [%0], %1;" :: "r"(mbar), "r"(cnt) : "memory")
#define MB_EXPECT_TX(mbar, tx) \
    asm volatile("mbarrier.arrive.expect_tx.shared.b64 _, [%0], %1;" :: "r"(mbar), "r"(tx) : "memory")
#define MB_ARRIVE(mbar) \
    asm volatile("mbarrier.arrive.shared.b64 _, [%0];" :: "r"(mbar) : "memory")

__device__ __forceinline__ void mb_wait_acq(uint32_t mbar, uint32_t parity) {
    uint32_t done = 0;
    while (!done) {
        asm volatile(
            "{\n\t.reg .pred p;\n\t"
            "mbarrier.try_wait.parity.acquire.cta.shared::cta.b64 p, [%1], %2, 0x989680;\n\t"
            "selp.b32 %0, 1, 0, p;\n\t}"
            : "=r"(done) : "r"(mbar), "r"(parity) : "memory");
    }
}
__device__ __forceinline__ void mb_wait_rlx(uint32_t mbar, uint32_t parity) {
    uint32_t done = 0;
    while (!done) {
        asm volatile(
            "{\n\t.reg .pred p;\n\t"
            "mbarrier.try_wait.parity.relaxed.cta.shared::cta.b64 p, [%1], %2, 0x989680;\n\t"
            "selp.b32 %0, 1, 0, p;\n\t}"
            : "=r"(done) : "r"(mbar), "r"(parity) : "memory");
    }
}

__global__ __launch_bounds__(THREADS, 1) void kmain(const float* __restrict__ f,
                                                    const float* __restrict__ w,
                                                    const int*   __restrict__ tw_words,
                                                    float* __restrict__ out) {
    const int bm = blockIdx.x;   // 0..7 (b*4+m)
    const int cg = blockIdx.y;   // 0..7
    const int vh = blockIdx.z;   // 0..1
    const int b  = bm >> 2;
    const int tid = threadIdx.x;
    const int lane = tid & 31, wid = tid >> 5;

    __shared__ float sred[NWARP][32];
    __shared__ float s_proto[2048];
    __shared__ float s_tw[32];
    __shared__ float s_cnt[8];
    __shared__ float s_aterm[48], s_acnt[48], s_sterm[48], s_scnt[48];
    __shared__ int   s_last;
    __shared__ __align__(8) unsigned long long mbars[2*NSLOT];

    // ---- dtype detect: one high-word per thread ----
    const int is64 = (__syncthreads_or(tw_words[2*tid + 1]) == 0);

    const uint32_t mb0 = (uint32_t)__cvta_generic_to_shared(mbars);
#define FULLB(i)  (mb0 + (i)*8)
#define EMPTYB(i) (mb0 + 48 + (i)*8)

    if (tid == 0) {
#pragma unroll
        for (int i = 0; i < NSLOT; i++) { MB_INIT(FULLB(i), 1); MB_INIT(EMPTYB(i), NWARP); }
    }
    __syncthreads();

    const long vbase = (long)vh * HALFV;
    const char*  fsrcB = (const char*)(f + ((long)bm*CCH + (long)cg*CB)*VV + vbase);
    const float* wsrc  = w + (long)bm*VV + vbase;
    const int4*  t32   = (const int4*)((const char*)tw_words + ((long)b*VV + vbase)*4) + tid;
    const int4*  t64   = (const int4*)((const char*)tw_words + ((long)b*VV + vbase)*8) + tid*2;

    const uint32_t sm0 = (uint32_t)__cvta_generic_to_shared(dynsm);

    // TMA: channels 0..3.  LDG: channels 4..7.
#define ISSUE(j, slot) do {                                                     \
        const uint32_t sb_ = sm0 + (slot)*STAGE_B;                              \
        MB_EXPECT_TX(FULLB(slot), STAGE_B);                                     \
        _Pragma("unroll")                                                       \
        for (int cc_ = 0; cc_ < CBT; cc_++)                                     \
            BULK(sb_ + cc_*CH_B, fsrcB + (long)(j)*CH_B + (long)cc_*(VV*4), CH_B, FULLB(slot)); \
    } while (0)

    float acc[CB][KK];
#pragma unroll
    for (int cc = 0; cc < CB; cc++)
#pragma unroll
        for (int k = 0; k < KK; k++) acc[cc][k] = 0.f;
    float twl[KK] = {0.f,0.f,0.f,0.f};
    float cl [KK] = {0.f,0.f,0.f,0.f};
    const bool doTW  = (cg == 0);
    const bool doCNT = doTW && ((bm & 3) == 0);

    if (tid == 0) {
#pragma unroll
        for (int j = 0; j < AHEAD; j++) ISSUE(j, j);
    }

    // w/t register prefetch for stage 0
    float4 wb = *(const float4*)(wsrc + tid*4);
    int4 ta = {0,0,0,0}, tb2 = {0,0,0,0};
    if (is64) { ta = t64[0]; tb2 = t64[1]; }
    else      { ta = t32[0]; }

#pragma unroll 1
    for (int s = 0; s < NSPC; s++) {
        // ---- LDG path: issue loads for channels 4..7, stage s (consumed below) ----
        float4 lv[4];
#pragma unroll
        for (int jc = 0; jc < 4; jc++)
            lv[jc] = *(const float4*)(fsrcB + (long)(4+jc)*(VV*4) + (long)s*CH_B + tid*16);

        // ---- producer: issue TMA stage j = s+AHEAD into slot j%6 ----
        const int j = s + AHEAD;
        if (tid == 0 && j < NSPC) {
            const int jslot = j % NSLOT;
            if (j >= NSLOT) mb_wait_rlx(EMPTYB(jslot), ((j / NSLOT) - 1) & 1);
            ISSUE(j, jslot);
        }
        // ---- prefetch next stage's w/t into regs ----
        float4 wn = {0.f,0.f,0.f,0.f};
        int4 tna = {0,0,0,0}, tnb = {0,0,0,0};
        if (s + 1 < NSPC) {
            wn = *(const float4*)(wsrc + (s+1)*SELEM + tid*4);
            if (is64) { tna = t64[(s+1)*768]; tnb = t64[(s+1)*768 + 1]; }
            else      { tna = t32[(s+1)*384]; }
        }

        // ---- consumer: wait TMA stage s ----
        const int cslot = s % NSLOT;
        mb_wait_acq(FULLB(cslot), (s / NSLOT) & 1);
        const char* sb = dynsm + cslot*STAGE_B;

        int t0, t1, t2, t3;
        if (is64) { t0 = ta.x; t1 = ta.z; t2 = tb2.x; t3 = tb2.z; }
        else      { t0 = ta.x; t1 = ta.y; t2 = ta.z;  t3 = ta.w; }
        const int   ts[4] = { t0, t1, t2, t3 };
        const float ws[4] = { wb.x, wb.y, wb.z, wb.w };
        float msk[4][KK];
#pragma unroll
        for (int jj = 0; jj < 4; jj++)
#pragma unroll
            for (int k = 0; k < KK; k++)
                msk[jj][k] = (ts[jj] == k) ? ws[jj] : 0.f;

        if (doTW) {
#pragma unroll
            for (int k = 0; k < KK; k++)
                twl[k] += (msk[0][k] + msk[1][k]) + (msk[2][k] + msk[3][k]);
        }
        if (doCNT) {
#pragma unroll
            for (int k = 0; k < KK; k++) {
                float c0 = (t0==k)?1.f:0.f, c1 = (t1==k)?1.f:0.f;
                float c2 = (t2==k)?1.f:0.f, c3 = (t3==k)?1.f:0.f;
                cl[k] += (c0+c1)+(c2+c3);
            }
        }

        // TMA channels 0..3 (from smem)
#pragma unroll
        for (int cc = 0; cc < CBT; cc++) {
            float4 fv = *(const float4*)(sb + cc*CH_B + tid*16);
            const float fs[4] = { fv.x, fv.y, fv.z, fv.w };
#pragma unroll
            for (int k = 0; k < KK; k++) {
                acc[cc][k] += fs[0]*msk[0][k];
                acc[cc][k] += fs[1]*msk[1][k];
                acc[cc][k] += fs[2]*msk[2][k];
                acc[cc][k] += fs[3]*msk[3][k];
            }
        }
        if (lane == 0) MB_ARRIVE(EMPTYB(cslot));

        // LDG channels 4..7 (from registers; loads had the whole wait to land)
#pragma unroll
        for (int jc = 0; jc < 4; jc++) {
            const float fs[4] = { lv[jc].x, lv[jc].y, lv[jc].z, lv[jc].w };
#pragma unroll
            for (int k = 0; k < KK; k++) {
                acc[4+jc][k] += fs[0]*msk[0][k];
                acc[4+jc][k] += fs[1]*msk[1][k];
                acc[4+jc][k] += fs[2]*msk[2][k];
                acc[4+jc][k] += fs[3]*msk[3][k];
            }
        }

        wb = wn; ta = tna; tb2 = tnb;
    }

    // ---- block-reduce 32 accumulators over 12 warps ----
#pragma unroll
    for (int cc = 0; cc < CB; cc++)
#pragma unroll
        for (int k = 0; k < KK; k++)
#pragma unroll
            for (int off = 16; off > 0; off >>= 1)
                acc[cc][k] += __shfl_down_sync(0xffffffffu, acc[cc][k], off);
    if (lane == 0) {
#pragma unroll
        for (int cc = 0; cc < CB; cc++)
#pragma unroll
            for (int k = 0; k < KK; k++) sred[wid][cc*KK + k] = acc[cc][k];
    }
    __syncthreads();
    const int bid = (bm*CG + cg)*VH + vh;
    if (tid < 32) {
        float s = 0.f;
#pragma unroll
        for (int ww = 0; ww < NWARP; ww++) s += sred[ww][tid];
        g_numpart[bid*32 + tid] = s;
    }
    __syncthreads();

    // ---- block-reduce tw/cnt ----
    {
        float vals[8];
#pragma unroll
        for (int jv = 0; jv < 4; jv++) { vals[jv] = twl[jv]; vals[4+jv] = cl[jv]; }
#pragma unroll
        for (int jv = 0; jv < 8; jv++)
#pragma unroll
            for (int off = 16; off > 0; off >>= 1)
                vals[jv] += __shfl_down_sync(0xffffffffu, vals[jv], off);
        if (lane == 0) {
#pragma unroll
            for (int jv = 0; jv < 8; jv++) sred[wid][jv] = vals[jv];
        }
        __syncthreads();
        if (tid < 8) {
            float s = 0.f;
#pragma unroll
            for (int ww = 0; ww < NWARP; ww++) s += sred[ww][tid];
            if (tid < 4) {
                if (doTW) g_twpart[(bm*VH + vh)*4 + tid] = s;
            } else {
                if (doCNT) g_cntpart[(b*VH + vh)*4 + (tid-4)] = s;
            }
        }
    }

    // ---- last-block-done finalize ----
    __threadfence();
    __syncthreads();
    if (tid == 0) {
        unsigned old = atomicAdd(&g_ctr, 1u);
        s_last = (old == (unsigned)(NBLK - 1));
    }
    __syncthreads();
    if (!s_last) return;

    // Phase A: tw (32) + cnt (8)
    if (tid < 32) {
        int bm_ = tid >> 2, k = tid & 3;
        float s = 0.f;
        for (int v = 0; v < VH; v++) s += g_twpart[(bm_*VH + v)*4 + k];
        s_tw[tid] = s + EPSL;
    } else if (tid < 40) {
        int jv = tid - 32, b_ = jv >> 2, k = jv & 3;
        float s = 0.f;
        for (int v = 0; v < VH; v++) s += g_cntpart[(b_*VH + v)*4 + k];
        s_cnt[jv] = s;
    }
    __syncthreads();

    // Phase B: proto raw = num / tw
    for (int cell = tid; cell < 2048; cell += THREADS) {
        int bm_ = cell >> 8;
        int rem = cell & 255;
        int c = rem >> 2, k = rem & 3;
        int cg_ = c >> 3, cc = c & 7;
        float s = 0.f;
        for (int v = 0; v < VH; v++)
            s += g_numpart[((bm_*CG + cg_)*VH + v)*32 + cc*4 + k];
        s_proto[(bm_*4 + k)*64 + c] = s / s_tw[bm_*4 + k];
    }
    __syncthreads();

    // Phase C: normalize 32 rows
    for (int r = wid; r < 32; r += NWARP) {
        float v1 = s_proto[r*64 + lane];
        float v2 = s_proto[r*64 + lane + 32];
        float ss = v1*v1 + v2*v2;
#pragma unroll
        for (int off = 16; off > 0; off >>= 1)
            ss += __shfl_xor_sync(0xffffffffu, ss, off);
        float norm = fmaxf(sqrtf(fmaxf(ss, 1e-24f)), 1e-12f);
        float inv = 1.f / norm;
        s_proto[r*64 + lane]      = v1 * inv;
        s_proto[r*64 + lane + 32] = v2 * inv;
    }
    __syncthreads();

    // Phase D: 96 pair dot products
    {
        const int p1t[6] = {0,0,0,1,1,2};
        const int p2t[6] = {1,2,3,2,3,3};
        for (int p = wid; p < 96; p += NWARP) {
            int r1, r2, outidx;
            bool val;
            bool isAlign = (p < 48);
            float om = 1.f;
            if (isAlign) {
                int pa = p;
                int b_ = pa / 24; int rem = pa % 24;
                int mp = rem >> 2, k = rem & 3;
                int m = p1t[mp], n = p2t[mp];
                r1 = (b_*4 + m)*4 + k;
                r2 = (b_*4 + n)*4 + k;
                val = (s_cnt[b_*4 + k] >= 1.f) && (k != 0);
                float cd = s_cnt[b_*4 + k] + EPSL;
                om = (s_tw[r1] / cd) * (s_tw[r2] / cd);
                outidx = pa;
            } else {
                int ps = p - 48;
                int b_ = ps / 24; int rem = ps % 24;
                int m = rem / 6, kp = rem % 6;
                int k1 = p1t[kp], k2 = p2t[kp];
                r1 = (b_*4 + m)*4 + k1;
                r2 = (b_*4 + m)*4 + k2;
                val = (s_cnt[b_*4 + k1] >= 1.f) && (k1 != 0) &&
                      (s_cnt[b_*4 + k2] >= 1.f) && (k2 != 0);
                outidx = ps;
            }
            float a1 = s_proto[r1*64 + lane],      b1 = s_proto[r2*64 + lane];
            float a2 = s_proto[r1*64 + lane + 32], b2 = s_proto[r2*64 + lane + 32];
            float dot = a1*b1 + a2*b2;
#pragma unroll
            for (int off = 16; off > 0; off >>= 1)
                dot += __shfl_xor_sync(0xffffffffu, dot, off);
            if (lane == 0) {
                if (isAlign) {
                    s_aterm[outidx] = val ? om * fmaxf(0.9f - dot, 0.f) : 0.f;
                    s_acnt[outidx]  = val ? 1.f : 0.f;
                } else {
                    s_sterm[outidx] = val ? fmaxf(dot - 0.1f, 0.f) : 0.f;
                    s_scnt[outidx]  = val ? 1.f : 0.f;
                }
            }
        }
    }
    __syncthreads();

    // Phase E: scalar loss + counter reset
    if (tid == 0) {
        float as = 0.f, ac = 0.f, ssum = 0.f, sc = 0.f;
        for (int i = 0; i < 48; i++) { as += s_aterm[i]; ac += s_acnt[i]; }
        for (int i = 0; i < 48; i++) { ssum += s_sterm[i]; sc += s_scnt[i]; }
        out[0] = as / (ac + EPSL) + ssum / (sc + EPSL);
        g_ctr = 0;
    }
}

extern "C" void kernel_launch(void* const* d_in, const int* in_sizes, int n_in,
                              void* d_out, int out_size) {
    const float* feats   = (const float*)d_in[0];
    const float* weights = (const float*)d_in[1];
    const int*   tgt_w   = (const int*)d_in[2];   // int32 or int64; detected on-device
    float* out = (float*)d_out;

    cudaFuncSetAttribute(kmain, cudaFuncAttributeMaxDynamicSharedMemorySize, DYN_BYTES);
    kmain<<<dim3(BB*MM, CG, VH), THREADS, DYN_BYTES>>>(feats, weights, tgt_w, out);
}